// round 17
// baseline (speedup 1.0000x reference)
#include <cuda_runtime.h>

// Sparsemax over rows of (B, 256) fp32 — persistent warps, 2 rows/warp,
// candidate compaction, L2 prefetch of the next pair (zero register cost).
//
// Recentered fixed point: q = round((z - zmax + 1)*2^14), w = q + 2^23.
// Warm start tau0 = zmax - 1  <=>  T0 = 2^23. ONE integer REDUX.ADD over
// active w gives sum (bits[0:23)) and count (bits[23:32)).
// tau update: T = umulhi(su - 2^14, m[c]) + 2^23, m[c]=(2^32-1)/c from a
// block-built shared table (floors -> superset-safe -> count-stable
// termination exact). Post-pass-1 active sets are subsets of the pass-1
// candidate set, which is COMPACTED to one candidate per lane (prefix scan +
// STS into zero-filled slots) -> each iteration costs 2 ALU ops + 1 REDUX
// per row. Warp-uniform fallback if a row has > 32 candidates.
// Output reconstructed from w: out = max((wf - Tf)*2^-14, 0).
//
// R16 profile: DRAM 69.7%, 7 waves -> load/compute/store phases alternate and
// wave transitions add tail. Here the grid is persistent (one resident wave);
// each warp walks pairs with stride = total warps and issues
// prefetch.global.L2 for its NEXT pair before computing the current one:
// DRAM streams under the ~700-cycle compute, and the next LDG hits L2.

static constexpr int D = 256;
static constexpr unsigned CBIT = 1u << 23;
static constexpr unsigned SMASK = CBIT - 1u;
static constexpr float QS = 16384.0f;              // 2^14
static constexpr float INVQ = 1.0f / 16384.0f;

__device__ __forceinline__ unsigned fmax_key(float m) {
    int bi = __float_as_int(m);
    return (bi >= 0) ? ((unsigned)bi | 0x80000000u) : (unsigned)(~bi);
}
__device__ __forceinline__ float key_fmax(unsigned key) {
    int bi = (key & 0x80000000u) ? (int)(key & 0x7fffffffu) : ~(int)key;
    return __int_as_float(bi);
}

__global__ void __launch_bounds__(256, 7) sparsemax_kernel(
    const float* __restrict__ in, float* __restrict__ out, int npairs)
{
    __shared__ unsigned s_recip[257];               // (2^32-1)/c
    __shared__ unsigned s_cand[8][2][32];           // [warp][row][slot]

    const int tid = threadIdx.x;
    s_recip[tid + 1] = 0xFFFFFFFFu / (unsigned)(tid + 1);
    __syncthreads();

    const int wid = tid >> 5;
    const int lane = tid & 31;
    const int nw = (gridDim.x * blockDim.x) >> 5;   // total warps
    int pair = (blockIdx.x * blockDim.x + tid) >> 5;

    for (; pair < npairs; pair += nw) {
        // Prefetch the NEXT pair's 2KB into L2 (16 lines of 128B, lanes 0-15).
        {
            const int np = pair + nw;
            if (np < npairs && lane < 16) {
                const char* pf = (const char*)in + (size_t)np * 2048 + lane * 128;
                asm volatile("prefetch.global.L2 [%0];" :: "l"(pf));
            }
        }

        const float4* gin = reinterpret_cast<const float4*>(in) + (size_t)pair * 128;
        float4 r0 = __ldcs(gin + lane);
        float4 r1 = __ldcs(gin + lane + 32);
        float4 r2 = __ldcs(gin + lane + 64);
        float4 r3 = __ldcs(gin + lane + 96);

        const float vA[8] = {r0.x, r0.y, r0.z, r0.w, r1.x, r1.y, r1.z, r1.w};
        const float vB[8] = {r2.x, r2.y, r2.z, r2.w, r3.x, r3.y, r3.z, r3.w};

        // Row maxima.
        float mA = fmaxf(fmaxf(fmaxf(vA[0], vA[1]), fmaxf(vA[2], vA[3])),
                         fmaxf(fmaxf(vA[4], vA[5]), fmaxf(vA[6], vA[7])));
        float mB = fmaxf(fmaxf(fmaxf(vB[0], vB[1]), fmaxf(vB[2], vB[3])),
                         fmaxf(fmaxf(vB[4], vB[5]), fmaxf(vB[6], vB[7])));
        unsigned kA = __reduce_max_sync(0xffffffffu, fmax_key(mA));
        unsigned kB = __reduce_max_sync(0xffffffffu, fmax_key(mB));

        // w = round((z - zmax + 1)*2^14) + 2^23.
        const float CA = fmaf(-key_fmax(kA), QS, 8404992.0f);
        const float CB = fmaf(-key_fmax(kB), QS, 8404992.0f);
        unsigned wA[8], wB[8];
        #pragma unroll
        for (int j = 0; j < 8; ++j) {
            wA[j] = (unsigned)__float2int_rn(fmaf(vA[j], QS, CA));
            wB[j] = (unsigned)__float2int_rn(fmaf(vB[j], QS, CB));
        }

        // Pass 1 at T0 = 2^23; per-lane accumulators (counts in bits 23+).
        unsigned laA = 0, laB = 0;
        #pragma unroll
        for (int j = 0; j < 8; ++j) {
            if (wA[j] > CBIT) laA += wA[j];
            if (wB[j] > CBIT) laB += wB[j];
        }
        unsigned aA = __reduce_add_sync(0xffffffffu, laA);
        unsigned aB = __reduce_add_sync(0xffffffffu, laB);
        unsigned cuA = aA >> 23, suA = aA & SMASK;
        unsigned cuB = aB >> 23, suB = aB & SMASK;
        unsigned cpA = cuA, cpB = cuB;
        unsigned TA = __umulhi(suA - 16384u, s_recip[cuA]) + CBIT;
        unsigned TB = __umulhi(suB - 16384u, s_recip[cuB]) + CBIT;

        if (cuA <= 32 && cuB <= 32) {
            __syncwarp();                            // s_cand reuse fence
            s_cand[wid][0][lane] = 0;
            s_cand[wid][1][lane] = 0;
            __syncwarp();
            unsigned cnt = (laA >> 23) | ((laB >> 23) << 8);
            unsigned scan = cnt;
            #pragma unroll
            for (int o = 1; o < 32; o <<= 1) {
                unsigned n = __shfl_up_sync(0xffffffffu, scan, o);
                if (lane >= o) scan += n;
            }
            scan -= cnt;                             // exclusive
            unsigned offA = scan & 0xffu;
            unsigned offB = (scan >> 8) & 0xffu;
            #pragma unroll
            for (int j = 0; j < 8; ++j) {
                if (wA[j] > CBIT) s_cand[wid][0][offA++] = wA[j];
                if (wB[j] > CBIT) s_cand[wid][1][offB++] = wB[j];
            }
            __syncwarp();
            const unsigned candA = s_cand[wid][0][lane];
            const unsigned candB = s_cand[wid][1][lane];

            #pragma unroll 1
            for (int it = 0; it < 32; ++it) {
                unsigned xA = (candA > TA) ? candA : 0u;
                unsigned xB = (candB > TB) ? candB : 0u;
                xA = __reduce_add_sync(0xffffffffu, xA);
                xB = __reduce_add_sync(0xffffffffu, xB);
                cuA = xA >> 23; suA = xA & SMASK;
                cuB = xB >> 23; suB = xB & SMASK;
                if (cuA == cpA && cuB == cpB) break;
                cpA = cuA; cpB = cuB;
                TA = __umulhi(suA - 16384u, s_recip[cuA]) + CBIT;
                TB = __umulhi(suB - 16384u, s_recip[cuB]) + CBIT;
            }
        } else {
            // Fallback (rare for this data; required in general).
            #pragma unroll 1
            for (int it = 0; it < 32; ++it) {
                unsigned xA = 0, xB = 0;
                #pragma unroll
                for (int j = 0; j < 8; ++j) {
                    if (wA[j] > TA) xA += wA[j];
                    if (wB[j] > TB) xB += wB[j];
                }
                xA = __reduce_add_sync(0xffffffffu, xA);
                xB = __reduce_add_sync(0xffffffffu, xB);
                cuA = xA >> 23; suA = xA & SMASK;
                cuB = xB >> 23; suB = xB & SMASK;
                if (cuA == cpA && cuB == cpB) break;
                cpA = cuA; cpB = cuB;
                TA = __umulhi(suA - 16384u, s_recip[cuA]) + CBIT;
                TB = __umulhi(suB - 16384u, s_recip[cuB]) + CBIT;
            }
        }

        // Output from w: out = max((wf - Tf)*2^-14, 0).
        const float tqA = __fdividef((float)(int)(suA - 16384u), (float)cuA);
        const float tqB = __fdividef((float)(int)(suB - 16384u), (float)cuB);
        const float cA2 = -(8388608.0f + tqA) * INVQ;
        const float cB2 = -(8388608.0f + tqB) * INVQ;

        float oA[8], oB[8];
        #pragma unroll
        for (int j = 0; j < 8; ++j) {
            oA[j] = fmaxf(fmaf((float)wA[j], INVQ, cA2), 0.0f);
            oB[j] = fmaxf(fmaf((float)wB[j], INVQ, cB2), 0.0f);
        }

        float4* gout = reinterpret_cast<float4*>(out) + (size_t)pair * 128;
        __stcs(gout + lane,      make_float4(oA[0], oA[1], oA[2], oA[3]));
        __stcs(gout + lane + 32, make_float4(oA[4], oA[5], oA[6], oA[7]));
        __stcs(gout + lane + 64, make_float4(oB[0], oB[1], oB[2], oB[3]));
        __stcs(gout + lane + 96, make_float4(oB[4], oB[5], oB[6], oB[7]));
    }
}

extern "C" void kernel_launch(void* const* d_in, const int* in_sizes, int n_in,
                              void* d_out, int out_size)
{
    const float* logits = (const float*)d_in[0];
    float* out = (float*)d_out;
    const int B = in_sizes[0] / D;     // 131072
    const int npairs = B / 2;          // 65536

    // Persistent grid: 7 blocks/SM on 148 SMs (56 warps/SM at <=36 regs).
    int grid = 148 * 7;
    int max_blocks = (npairs + 7) / 8;
    if (grid > max_blocks) grid = max_blocks;
    sparsemax_kernel<<<grid, 256>>>(logits, out, npairs);
}